// round 2
// baseline (speedup 1.0000x reference)
#include <cuda_runtime.h>
#include <cuda_bf16.h>

// Problem constants
#define B_   16
#define K_   256
#define T_   64
#define D_   128
#define C1   (-0.8f)   // (ALPHA - 1)

// Scratch (device globals: allocation-free rule)
__device__ float g_U [B_*K_*D_];   // u[b,k,d]
__device__ float g_Vb[B_*K_*D_];   // v[b,k,d] + b_lin[d]
__device__ float g_P [B_*K_];      // sum_d a_d * u
__device__ float g_Q [B_*K_];      // sum_d a_d * vb

// ---------------------------------------------------------------------------
// Kernel A: projections u = x@W1^T, vb = x@W2^T + b_lin, plus P/Q reductions.
// Grid 128 blocks x 128 threads; each block handles 32 rows (b,k).
// W staged in smem with stride-129 pad (conflict-free: bank = (d+t) mod 32).
// ---------------------------------------------------------------------------
#define KA_ROWS 32
#define KA_SMEM_FLOATS (128*129 + 64 + 128 + 128 + 8)

__global__ void __launch_bounds__(128)
kA(const float* __restrict__ x, const float* __restrict__ W,
   const float* __restrict__ b_lin, const float* __restrict__ a)
{
    extern __shared__ float sm[];
    float* Ws   = sm;                 // 128*129
    float* xs   = Ws + 128*129;       // 64
    float* as_  = xs + 64;            // 128
    float* bls  = as_ + 128;          // 128
    float* redP = bls + 128;          // 4
    float* redQ = redP + 4;           // 4

    const int tid = threadIdx.x;
    // coalesced W load -> padded smem
    for (int idx = tid; idx < 128*128; idx += 128)
        Ws[(idx >> 7)*129 + (idx & 127)] = W[idx];
    as_[tid] = a[tid];
    bls[tid] = b_lin[tid];
    __syncthreads();

    const int d    = tid;
    const int lane = tid & 31;
    const int wrp  = tid >> 5;
    const float ad = as_[d];
    const float bd = bls[d];
    const float* wr = Ws + d*129;

    for (int r = 0; r < KA_ROWS; r++) {
        const int row = blockIdx.x * KA_ROWS + r;   // = b*K_ + k
        if (tid < 64) xs[tid] = x[row*T_ + tid];
        __syncthreads();

        float u = 0.f, v = 0.f;
        #pragma unroll 8
        for (int t = 0; t < T_; t++) {
            const float xv = xs[t];
            u = fmaf(xv, wr[t],      u);
            v = fmaf(xv, wr[64 + t], v);
        }
        v += bd;
        g_U [row*D_ + d] = u;
        g_Vb[row*D_ + d] = v;

        float pa = ad * u, qa = ad * v;
        #pragma unroll
        for (int off = 16; off; off >>= 1) {
            pa += __shfl_down_sync(0xffffffffu, pa, off);
            qa += __shfl_down_sync(0xffffffffu, qa, off);
        }
        if (lane == 0) { redP[wrp] = pa; redQ[wrp] = qa; }
        __syncthreads();
        if (tid == 0) {
            g_P[row] = redP[0] + redP[1] + redP[2] + redP[3];
            g_Q[row] = redQ[0] + redQ[1] + redQ[2] + redQ[3];
        }
        __syncthreads();   // protect xs/red before next iteration's writes
    }
}

// ---------------------------------------------------------------------------
// Kernel B: e-scores + softmax + attention@x + sigmoid, fused per (b, 16 i's).
// Grid (16 i-groups, 16 b), 256 threads = 8 warps; each warp owns 2 i rows.
// Vb[b] resident in smem, row pad 132 floats (LDS.128 conflict-free for
// lane-varying j). Epilogue overlays x[b] onto the Vb region.
// ---------------------------------------------------------------------------
#define VBS_F   (K_*132)              // 33792 floats
#define US_OFF  (VBS_F)               // 16*132 = 2112
#define AS_OFF  (US_OFF + 16*132)     // 35904
#define QS_OFF  (AS_OFF + 128)        // 36032
#define WS_OFF  (QS_OFF + 256)        // 36288
#define KB_SMEM_FLOATS (WS_OFF + K_*16)   // 40384 floats = 161536 B

__global__ void __launch_bounds__(256)
kB(const float* __restrict__ x, const float* __restrict__ a,
   const float* __restrict__ bias, float* __restrict__ out)
{
    extern __shared__ float sm[];
    float* Vbs = sm;
    float* Us  = sm + US_OFF;
    float* as_ = sm + AS_OFF;
    float* Qs  = sm + QS_OFF;
    float* ws  = sm + WS_OFF;   // ws[j][i_local], 256 x 16

    const int tid = threadIdx.x;
    const int b   = blockIdx.y;
    const int bx  = blockIdx.x;          // i-group (16 i rows)
    const int igbase = bx * 16;

    // ---- stage Vb[b], U rows, a, Q into smem (vectorized, coalesced) ----
    {
        const float4* vg4  = (const float4*)g_Vb + b * (K_*D_/4);
        float4*       vbs4 = (float4*)Vbs;
        for (int idx = tid; idx < K_*D_/4; idx += 256) {
            const int j = idx >> 5, c = idx & 31;
            vbs4[j*33 + c] = vg4[idx];
        }
        const float4* ug4 = (const float4*)g_U + (b*K_ + igbase) * (D_/4);
        float4*       us4 = (float4*)Us;
        for (int idx = tid; idx < 16*D_/4; idx += 256) {
            const int il = idx >> 5, c = idx & 31;
            us4[il*33 + c] = ug4[idx];
        }
        if (tid < 128) as_[tid] = a[tid];
        Qs[tid] = g_Q[b*K_ + tid];
    }
    __syncthreads();

    const int w  = tid >> 5;
    const int l  = tid & 31;
    const int i0 = 2*w, i1 = 2*w + 1;

    // ---- e-loop: acc[ii][jb] = sum_d a_d * min(u_id + vb_jd, 0) ----
    float acc[2][8];
    #pragma unroll
    for (int ii = 0; ii < 2; ii++)
        #pragma unroll
        for (int jb = 0; jb < 8; jb++) acc[ii][jb] = 0.f;

    {
        const float4* vbs4 = (const float4*)Vbs;
        const float4* us4  = (const float4*)Us;
        const float4* a4   = (const float4*)as_;
        for (int dc = 0; dc < 32; dc++) {
            const float4 u0 = us4[i0*33 + dc];
            const float4 u1 = us4[i1*33 + dc];
            const float4 av = a4[dc];
            #pragma unroll
            for (int jb = 0; jb < 8; jb++) {
                const float4 vv = vbs4[(jb*32 + l)*33 + dc];
                float z;
                z = u0.x + vv.x; acc[0][jb] = fmaf(fminf(z, 0.f), av.x, acc[0][jb]);
                z = u0.y + vv.y; acc[0][jb] = fmaf(fminf(z, 0.f), av.y, acc[0][jb]);
                z = u0.z + vv.z; acc[0][jb] = fmaf(fminf(z, 0.f), av.z, acc[0][jb]);
                z = u0.w + vv.w; acc[0][jb] = fmaf(fminf(z, 0.f), av.w, acc[0][jb]);
                z = u1.x + vv.x; acc[1][jb] = fmaf(fminf(z, 0.f), av.x, acc[1][jb]);
                z = u1.y + vv.y; acc[1][jb] = fmaf(fminf(z, 0.f), av.y, acc[1][jb]);
                z = u1.z + vv.z; acc[1][jb] = fmaf(fminf(z, 0.f), av.z, acc[1][jb]);
                z = u1.w + vv.w; acc[1][jb] = fmaf(fminf(z, 0.f), av.w, acc[1][jb]);
            }
        }
    }

    // ---- finish e, softmax over j (in-warp), stash weights to smem ----
    #pragma unroll
    for (int ii = 0; ii < 2; ii++) {
        const int il = i0 + ii;
        const int ig = igbase + il;
        const float P = g_P[b*K_ + ig];
        const float* brow = bias + ig*K_;
        float e[8];
        float m = -1e30f;
        #pragma unroll
        for (int jb = 0; jb < 8; jb++) {
            const int j = jb*32 + l;
            const float ev = P + Qs[j] + C1*acc[ii][jb] + brow[j];
            e[jb] = ev;
            m = fmaxf(m, ev);
        }
        #pragma unroll
        for (int off = 16; off; off >>= 1)
            m = fmaxf(m, __shfl_xor_sync(0xffffffffu, m, off));
        float s = 0.f;
        #pragma unroll
        for (int jb = 0; jb < 8; jb++) { e[jb] = __expf(e[jb] - m); s += e[jb]; }
        #pragma unroll
        for (int off = 16; off; off >>= 1)
            s += __shfl_xor_sync(0xffffffffu, s, off);
        const float inv = __fdividef(1.f, s);
        #pragma unroll
        for (int jb = 0; jb < 8; jb++)
            ws[(jb*32 + l)*16 + il] = e[jb] * inv;
    }
    __syncthreads();

    // ---- overlay x[b] onto the (now dead) Vb smem region ----
    {
        float4*       xs4 = (float4*)sm;
        const float4* xg4 = (const float4*)x + b * (K_*T_/4);
        for (int idx = tid; idx < K_*T_/4; idx += 256) xs4[idx] = xg4[idx];
    }
    __syncthreads();

    // ---- epilogue: h[i,t] = sigmoid( sum_j w_ij * x[b,j,t] ) ----
    {
        const float2* xs2 = (const float2*)sm;   // x[j][t] row-major, t pair per lane
        float h00 = 0.f, h01 = 0.f, h10 = 0.f, h11 = 0.f;
        #pragma unroll 8
        for (int j = 0; j < K_; j++) {
            const float2 wv = *(const float2*)(ws + j*16 + i0);   // (w_i0, w_i1)
            const float2 xv = xs2[j*32 + l];                       // x[j][2l], x[j][2l+1]
            h00 = fmaf(wv.x, xv.x, h00);
            h01 = fmaf(wv.x, xv.y, h01);
            h10 = fmaf(wv.y, xv.x, h10);
            h11 = fmaf(wv.y, xv.y, h11);
        }
        const int row0 = (b*K_ + igbase + i0)*T_ + 2*l;
        const int row1 = row0 + T_;
        float2 o0, o1;
        o0.x = __fdividef(1.f, 1.f + __expf(-h00));
        o0.y = __fdividef(1.f, 1.f + __expf(-h01));
        o1.x = __fdividef(1.f, 1.f + __expf(-h10));
        o1.y = __fdividef(1.f, 1.f + __expf(-h11));
        *(float2*)(out + row0) = o0;
        *(float2*)(out + row1) = o1;
    }
}

// ---------------------------------------------------------------------------
extern "C" void kernel_launch(void* const* d_in, const int* in_sizes, int n_in,
                              void* d_out, int out_size)
{
    const float* x     = (const float*)d_in[0];
    // d_in[1] = embedding (unused by the reference computation)
    const float* W     = (const float*)d_in[2];
    const float* b_lin = (const float*)d_in[3];
    const float* a     = (const float*)d_in[4];
    const float* bias  = (const float*)d_in[5];
    float* out = (float*)d_out;

    const int smemA = KA_SMEM_FLOATS * 4;   // 67360 B
    const int smemB = KB_SMEM_FLOATS * 4;   // 161536 B
    cudaFuncSetAttribute(kA, cudaFuncAttributeMaxDynamicSharedMemorySize, smemA);
    cudaFuncSetAttribute(kB, cudaFuncAttributeMaxDynamicSharedMemorySize, smemB);

    kA<<<128, 128, smemA>>>(x, W, b_lin, a);
    kB<<<dim3(16, 16), 256, smemB>>>(x, a, bias, out);
}

// round 3
// speedup vs baseline: 1.7773x; 1.7773x over previous
#include <cuda_runtime.h>
#include <cuda_bf16.h>

// Problem constants
#define B_   16
#define K_   256
#define T_   64
#define D_   128
#define C1   (-0.8f)   // (ALPHA - 1)

// Scratch (device globals: allocation-free rule)
__device__ float g_U [B_*K_*D_];   // u[b,k,d]
__device__ float g_Vb[B_*K_*D_];   // v[b,k,d] + b_lin[d]

// ---------------------------------------------------------------------------
// Kernel A: register-tiled GEMM.  C[4096 x 256] = x[4096 x 64] @ Wr[256 x 64]^T
// where Wr[n] = W[n][0:64] (n<128, -> u) or W[n-128][64:128] (n>=128, -> vb).
// Grid 128 blocks x 256 threads; block = 32 rows x 256 cols; thread = 4x8.
// Pad 68 floats/row: lane l reads Ws[(l+32nn)*68+..] -> banks 4l mod 32,
// conflict-free float4 phases.
// ---------------------------------------------------------------------------
#define PADA 68
#define KA_SMEM_FLOATS (256*PADA + 32*PADA)   // 19584 floats = 78336 B

__global__ void __launch_bounds__(256)
kA(const float* __restrict__ x, const float* __restrict__ W,
   const float* __restrict__ b_lin)
{
    extern __shared__ float sm[];
    float* Ws = sm;               // 256 x 68
    float* xs = sm + 256*PADA;    // 32 x 68

    const int tid  = threadIdx.x;
    const int row0 = blockIdx.x * 32;

    // stage Wr (both halves of W, re-indexed), coalesced reads
    for (int idx = tid; idx < 256*64; idx += 256) {
        const int n = idx >> 6, t = idx & 63;
        Ws[n*PADA + t] = (n < 128) ? W[n*128 + t] : W[(n-128)*128 + 64 + t];
    }
    // stage x rows for this block
    for (int idx = tid; idx < 32*64; idx += 256) {
        const int r = idx >> 6, t = idx & 63;
        xs[r*PADA + t] = x[(row0 + r)*T_ + t];
    }
    __syncthreads();

    const int l = tid & 31;     // lane -> col group base
    const int w = tid >> 5;     // warp -> rows 4w..4w+3

    float acc[4][8];
    #pragma unroll
    for (int r = 0; r < 4; r++)
        #pragma unroll
        for (int nn = 0; nn < 8; nn++) acc[r][nn] = 0.f;

    #pragma unroll 4
    for (int k4 = 0; k4 < 16; k4++) {
        float4 xv[4], wv[8];
        #pragma unroll
        for (int r = 0; r < 4; r++)
            xv[r] = *(const float4*)(xs + (4*w + r)*PADA + 4*k4);
        #pragma unroll
        for (int nn = 0; nn < 8; nn++)
            wv[nn] = *(const float4*)(Ws + (l + 32*nn)*PADA + 4*k4);
        #pragma unroll
        for (int r = 0; r < 4; r++)
            #pragma unroll
            for (int nn = 0; nn < 8; nn++) {
                acc[r][nn] = fmaf(xv[r].x, wv[nn].x, acc[r][nn]);
                acc[r][nn] = fmaf(xv[r].y, wv[nn].y, acc[r][nn]);
                acc[r][nn] = fmaf(xv[r].z, wv[nn].z, acc[r][nn]);
                acc[r][nn] = fmaf(xv[r].w, wv[nn].w, acc[r][nn]);
            }
    }

    float bl[4];
    #pragma unroll
    for (int nn = 0; nn < 4; nn++) bl[nn] = __ldg(b_lin + l + 32*nn);

    #pragma unroll
    for (int r = 0; r < 4; r++) {
        const int row = row0 + 4*w + r;
        #pragma unroll
        for (int nn = 0; nn < 4; nn++)
            g_U[row*D_ + l + 32*nn] = acc[r][nn];
        #pragma unroll
        for (int nn = 0; nn < 4; nn++)
            g_Vb[row*D_ + l + 32*nn] = acc[r][nn + 4] + bl[nn];
    }
}

// ---------------------------------------------------------------------------
// Kernel B: e-scores + softmax + attention@x + sigmoid.
// Grid (8 i-groups x 16 b) = 128 blocks (one wave), 512 threads = 16 warps.
// Each warp owns 2 of the block's 32 i-rows. Vb[b] resident in smem
// (132-float row pad, conflict-free LDS.128). P/Q computed in-prologue.
// ---------------------------------------------------------------------------
#define VBS_F   (K_*132)                  // 33792
#define US_OFF  (VBS_F)                   // + 32*132 = 4224
#define AS_OFF  (US_OFF + 32*132)         // 38016
#define QS_OFF  (AS_OFF + 128)            // 38144
#define PS_OFF  (QS_OFF + 256)            // 38400
#define WS_OFF  (PS_OFF + 32)             // 38432
#define KB_SMEM_FLOATS (WS_OFF + K_*33)   // 46880 floats = 187520 B

__global__ void __launch_bounds__(512)
kB(const float* __restrict__ x, const float* __restrict__ a,
   const float* __restrict__ bias, float* __restrict__ out)
{
    extern __shared__ float sm[];
    float* Vbs = sm;
    float* Us  = sm + US_OFF;
    float* as_ = sm + AS_OFF;
    float* Qs  = sm + QS_OFF;
    float* Ps  = sm + PS_OFF;
    float* ws  = sm + WS_OFF;   // ws[j*33 + il]

    const int tid = threadIdx.x;
    const int b   = blockIdx.y;
    const int igbase = blockIdx.x * 32;

    // ---- stage Vb[b], 32 U rows, a ----
    {
        const float4* vg4  = (const float4*)g_Vb + b * (K_*D_/4);
        float4*       vbs4 = (float4*)Vbs;
        for (int idx = tid; idx < K_*D_/4; idx += 512) {
            const int j = idx >> 5, c = idx & 31;
            vbs4[j*33 + c] = vg4[idx];
        }
        const float4* ug4 = (const float4*)g_U + (b*K_ + igbase) * (D_/4);
        float4*       us4 = (float4*)Us;
        for (int idx = tid; idx < 32*D_/4; idx += 512) {
            const int il = idx >> 5, c = idx & 31;
            us4[il*33 + c] = ug4[idx];
        }
        if (tid < 128) as_[tid] = a[tid];
    }
    __syncthreads();

    // ---- P/Q prologue: Q[j] = sum_d a_d*vb,  P[il] = sum_d a_d*u ----
    if (tid < 256) {
        const float4* a4 = (const float4*)as_;
        const float4* v4 = (const float4*)Vbs + tid*33;
        float q = 0.f;
        #pragma unroll 8
        for (int dc = 0; dc < 32; dc++) {
            const float4 av = a4[dc], vv = v4[dc];
            q += av.x*vv.x + av.y*vv.y + av.z*vv.z + av.w*vv.w;
        }
        Qs[tid] = q;
    } else if (tid < 288) {
        const int il = tid - 256;
        const float4* a4 = (const float4*)as_;
        const float4* u4 = (const float4*)Us + il*33;
        float p = 0.f;
        #pragma unroll 8
        for (int dc = 0; dc < 32; dc++) {
            const float4 av = a4[dc], uv = u4[dc];
            p += av.x*uv.x + av.y*uv.y + av.z*uv.z + av.w*uv.w;
        }
        Ps[il] = p;
    }
    __syncthreads();

    const int w  = tid >> 5;
    const int l  = tid & 31;
    const int i0 = 2*w, i1 = 2*w + 1;

    // ---- e-loop: acc[ii][jb] = sum_d a_d * min(u_id + vb_jd, 0) ----
    float acc[2][8];
    #pragma unroll
    for (int ii = 0; ii < 2; ii++)
        #pragma unroll
        for (int jb = 0; jb < 8; jb++) acc[ii][jb] = 0.f;

    {
        const float4* vbs4 = (const float4*)Vbs;
        const float4* us4  = (const float4*)Us;
        const float4* a4   = (const float4*)as_;
        for (int dc = 0; dc < 32; dc++) {
            const float4 u0 = us4[i0*33 + dc];
            const float4 u1 = us4[i1*33 + dc];
            const float4 av = a4[dc];
            #pragma unroll
            for (int jb = 0; jb < 8; jb++) {
                const float4 vv = vbs4[(jb*32 + l)*33 + dc];
                float z;
                z = u0.x + vv.x; acc[0][jb] = fmaf(fminf(z, 0.f), av.x, acc[0][jb]);
                z = u0.y + vv.y; acc[0][jb] = fmaf(fminf(z, 0.f), av.y, acc[0][jb]);
                z = u0.z + vv.z; acc[0][jb] = fmaf(fminf(z, 0.f), av.z, acc[0][jb]);
                z = u0.w + vv.w; acc[0][jb] = fmaf(fminf(z, 0.f), av.w, acc[0][jb]);
                z = u1.x + vv.x; acc[1][jb] = fmaf(fminf(z, 0.f), av.x, acc[1][jb]);
                z = u1.y + vv.y; acc[1][jb] = fmaf(fminf(z, 0.f), av.y, acc[1][jb]);
                z = u1.z + vv.z; acc[1][jb] = fmaf(fminf(z, 0.f), av.z, acc[1][jb]);
                z = u1.w + vv.w; acc[1][jb] = fmaf(fminf(z, 0.f), av.w, acc[1][jb]);
            }
        }
    }

    // ---- finish e, softmax over j (in-warp), stash weights ----
    #pragma unroll
    for (int ii = 0; ii < 2; ii++) {
        const int il = i0 + ii;
        const int ig = igbase + il;
        const float P = Ps[il];
        const float* brow = bias + ig*K_;
        float e[8];
        float m = -1e30f;
        #pragma unroll
        for (int jb = 0; jb < 8; jb++) {
            const int j = jb*32 + l;
            const float ev = P + Qs[j] + C1*acc[ii][jb] + brow[j];
            e[jb] = ev;
            m = fmaxf(m, ev);
        }
        #pragma unroll
        for (int off = 16; off; off >>= 1)
            m = fmaxf(m, __shfl_xor_sync(0xffffffffu, m, off));
        float s = 0.f;
        #pragma unroll
        for (int jb = 0; jb < 8; jb++) { e[jb] = __expf(e[jb] - m); s += e[jb]; }
        #pragma unroll
        for (int off = 16; off; off >>= 1)
            s += __shfl_xor_sync(0xffffffffu, s, off);
        const float inv = __fdividef(1.f, s);
        #pragma unroll
        for (int jb = 0; jb < 8; jb++)
            ws[(jb*32 + l)*33 + il] = e[jb] * inv;   // stride 33: conflict-free
    }
    __syncthreads();

    // ---- overlay x[b] onto the (now dead) Vb smem region ----
    {
        float4*       xs4 = (float4*)sm;
        const float4* xg4 = (const float4*)x + b * (K_*T_/4);
        for (int idx = tid; idx < K_*T_/4; idx += 512) xs4[idx] = xg4[idx];
    }
    __syncthreads();

    // ---- epilogue: h[i,t] = sigmoid( sum_j w_ij * x[b,j,t] ) ----
    {
        const float2* xs2 = (const float2*)sm;   // x[j][t], lane t-pair
        float h00 = 0.f, h01 = 0.f, h10 = 0.f, h11 = 0.f;
        #pragma unroll 8
        for (int j = 0; j < K_; j++) {
            const float w0 = ws[j*33 + i0];
            const float w1 = ws[j*33 + i1];
            const float2 xv = xs2[j*32 + l];
            h00 = fmaf(w0, xv.x, h00);
            h01 = fmaf(w0, xv.y, h01);
            h10 = fmaf(w1, xv.x, h10);
            h11 = fmaf(w1, xv.y, h11);
        }
        const int row0 = (b*K_ + igbase + i0)*T_ + 2*l;
        const int row1 = row0 + T_;
        float2 o0, o1;
        o0.x = __fdividef(1.f, 1.f + __expf(-h00));
        o0.y = __fdividef(1.f, 1.f + __expf(-h01));
        o1.x = __fdividef(1.f, 1.f + __expf(-h10));
        o1.y = __fdividef(1.f, 1.f + __expf(-h11));
        *(float2*)(out + row0) = o0;
        *(float2*)(out + row1) = o1;
    }
}

// ---------------------------------------------------------------------------
extern "C" void kernel_launch(void* const* d_in, const int* in_sizes, int n_in,
                              void* d_out, int out_size)
{
    const float* x     = (const float*)d_in[0];
    // d_in[1] = embedding (unused by the reference computation)
    const float* W     = (const float*)d_in[2];
    const float* b_lin = (const float*)d_in[3];
    const float* a     = (const float*)d_in[4];
    const float* bias  = (const float*)d_in[5];
    float* out = (float*)d_out;

    const int smemA = KA_SMEM_FLOATS * 4;   // 78336 B
    const int smemB = KB_SMEM_FLOATS * 4;   // 187520 B
    cudaFuncSetAttribute(kA, cudaFuncAttributeMaxDynamicSharedMemorySize, smemA);
    cudaFuncSetAttribute(kB, cudaFuncAttributeMaxDynamicSharedMemorySize, smemB);

    kA<<<128, 256, smemA>>>(x, W, b_lin);
    kB<<<dim3(8, 16), 512, smemB>>>(x, a, bias, out);
}

// round 4
// speedup vs baseline: 1.9430x; 1.0933x over previous
#include <cuda_runtime.h>
#include <cuda_bf16.h>

typedef unsigned long long u64;

// Problem constants
#define B_   16
#define K_   256
#define T_   64
#define D_   128
// e = C_LIN*(P+Q) + C_ABS*sum_d a_d*|u+vb| + bias   (alpha = 0.2)
#define C_LIN 0.6f
#define C_ABS 0.4f
#define ABSMASK2 0x7FFFFFFF7FFFFFFFULL

__device__ __forceinline__ u64 addx2(u64 a, u64 b) {
    u64 r; asm("add.rn.f32x2 %0,%1,%2;" : "=l"(r) : "l"(a), "l"(b)); return r;
}
__device__ __forceinline__ u64 fmax2p(u64 a, u64 b, u64 c) {
    u64 r; asm("fma.rn.f32x2 %0,%1,%2,%3;" : "=l"(r) : "l"(a), "l"(b), "l"(c)); return r;
}
__device__ __forceinline__ u64 dup2(float v) {
    u64 r; asm("mov.b64 %0, {%1, %1};" : "=l"(r) : "f"(v)); return r;
}
__device__ __forceinline__ float lo32(u64 v) { return __uint_as_float((unsigned)v); }
__device__ __forceinline__ float hi32(u64 v) { return __uint_as_float((unsigned)(v >> 32)); }

// Scratch (device globals: allocation-free rule)
__device__ float g_U [B_*K_*D_];   // u[b,k,d]
__device__ float g_Vb[B_*K_*D_];   // v[b,k,d] + b_lin[d]

// ---------------------------------------------------------------------------
// Kernel A: register-tiled GEMM with packed f32x2 FMAs.
// C[4096 x 256] = x[4096 x 64] @ Wr[256 x 64]^T
// Grid 128 blocks x 256 threads; block = 32 rows x 256 cols; thread = 4x8.
// ---------------------------------------------------------------------------
#define PADA 68
#define KA_SMEM_FLOATS (256*PADA + 32*PADA)   // 19584 floats = 78336 B

__global__ void __launch_bounds__(256)
kA(const float* __restrict__ x, const float* __restrict__ W,
   const float* __restrict__ b_lin)
{
    extern __shared__ float sm[];
    float* Ws = sm;               // 256 x 68
    float* xs = sm + 256*PADA;    // 32 x 68

    const int tid  = threadIdx.x;
    const int row0 = blockIdx.x * 32;

    for (int idx = tid; idx < 256*64; idx += 256) {
        const int n = idx >> 6, t = idx & 63;
        Ws[n*PADA + t] = (n < 128) ? W[n*128 + t] : W[(n-128)*128 + 64 + t];
    }
    for (int idx = tid; idx < 32*64; idx += 256) {
        const int r = idx >> 6, t = idx & 63;
        xs[r*PADA + t] = x[(row0 + r)*T_ + t];
    }
    __syncthreads();

    const int l = tid & 31;
    const int w = tid >> 5;

    u64 acc2[4][8];
    #pragma unroll
    for (int r = 0; r < 4; r++)
        #pragma unroll
        for (int nn = 0; nn < 8; nn++) acc2[r][nn] = 0ull;

    #pragma unroll 4
    for (int k4 = 0; k4 < 16; k4++) {
        ulonglong2 xv[4], wv[8];
        #pragma unroll
        for (int r = 0; r < 4; r++)
            xv[r] = *(const ulonglong2*)(xs + (4*w + r)*PADA + 4*k4);
        #pragma unroll
        for (int nn = 0; nn < 8; nn++)
            wv[nn] = *(const ulonglong2*)(Ws + (l + 32*nn)*PADA + 4*k4);
        #pragma unroll
        for (int r = 0; r < 4; r++)
            #pragma unroll
            for (int nn = 0; nn < 8; nn++) {
                acc2[r][nn] = fmax2p(xv[r].x, wv[nn].x, acc2[r][nn]);
                acc2[r][nn] = fmax2p(xv[r].y, wv[nn].y, acc2[r][nn]);
            }
    }

    float bl[4];
    #pragma unroll
    for (int nn = 0; nn < 4; nn++) bl[nn] = __ldg(b_lin + l + 32*nn);

    #pragma unroll
    for (int r = 0; r < 4; r++) {
        const int row = row0 + 4*w + r;
        #pragma unroll
        for (int nn = 0; nn < 4; nn++)
            g_U[row*D_ + l + 32*nn] = lo32(acc2[r][nn]) + hi32(acc2[r][nn]);
        #pragma unroll
        for (int nn = 0; nn < 4; nn++)
            g_Vb[row*D_ + l + 32*nn] = lo32(acc2[r][nn+4]) + hi32(acc2[r][nn+4]) + bl[nn];
    }
}

// ---------------------------------------------------------------------------
// Kernel B: abs-sum e-scores (packed f32x2) + softmax + attention@x + sigmoid.
// Grid (8 i-groups x 16 b) = 128 blocks, 512 threads = 16 warps.
// Each warp owns 2 i rows. Vb[b] resident in smem (132-float row pad).
// ---------------------------------------------------------------------------
#define VBS_F   (K_*132)                  // 33792
#define US_OFF  (VBS_F)                   // + 32*132 = 4224
#define AS_OFF  (US_OFF + 32*132)         // 38016
#define QS_OFF  (AS_OFF + 128)            // 38144
#define PS_OFF  (QS_OFF + 256)            // 38400
#define WS_OFF  (PS_OFF + 32)             // 38432
#define KB_SMEM_FLOATS (WS_OFF + K_*34)   // 47136 floats = 188544 B

__global__ void __launch_bounds__(512)
kB(const float* __restrict__ x, const float* __restrict__ a,
   const float* __restrict__ bias, float* __restrict__ out)
{
    extern __shared__ float sm[];
    float* Vbs = sm;
    float* Us  = sm + US_OFF;
    float* as_ = sm + AS_OFF;
    float* Qs  = sm + QS_OFF;
    float* Ps  = sm + PS_OFF;
    float* ws  = sm + WS_OFF;   // ws[j*34 + il]

    const int tid = threadIdx.x;
    const int b   = blockIdx.y;
    const int igbase = blockIdx.x * 32;

    // ---- stage Vb[b], 32 U rows, a ----
    {
        const float4* vg4  = (const float4*)g_Vb + b * (K_*D_/4);
        float4*       vbs4 = (float4*)Vbs;
        for (int idx = tid; idx < K_*D_/4; idx += 512) {
            const int j = idx >> 5, c = idx & 31;
            vbs4[j*33 + c] = vg4[idx];
        }
        const float4* ug4 = (const float4*)g_U + (b*K_ + igbase) * (D_/4);
        float4*       us4 = (float4*)Us;
        for (int idx = tid; idx < 32*D_/4; idx += 512) {
            const int il = idx >> 5, c = idx & 31;
            us4[il*33 + c] = ug4[idx];
        }
        if (tid < 128) as_[tid] = a[tid];
    }
    __syncthreads();

    // ---- P/Q prologue: Q[j] = sum_d a_d*vb,  P[il] = sum_d a_d*u ----
    if (tid < 256) {
        const float4* a4 = (const float4*)as_;
        const float4* v4 = (const float4*)Vbs + tid*33;
        float q = 0.f;
        #pragma unroll 8
        for (int dc = 0; dc < 32; dc++) {
            const float4 av = a4[dc], vv = v4[dc];
            q += av.x*vv.x + av.y*vv.y + av.z*vv.z + av.w*vv.w;
        }
        Qs[tid] = q;
    } else if (tid < 288) {
        const int il = tid - 256;
        const float4* a4 = (const float4*)as_;
        const float4* u4 = (const float4*)Us + il*33;
        float p = 0.f;
        #pragma unroll 8
        for (int dc = 0; dc < 32; dc++) {
            const float4 av = a4[dc], uv = u4[dc];
            p += av.x*uv.x + av.y*uv.y + av.z*uv.z + av.w*uv.w;
        }
        Ps[il] = p;
    }
    __syncthreads();

    const int w  = tid >> 5;
    const int l  = tid & 31;
    const int i0 = 2*w, i1 = 2*w + 1;

    // ---- e-loop (packed): acc2 = sum_d a_d * |u_id + vb_jd|  (2 d per lane) --
    u64 acc2[2][8];
    #pragma unroll
    for (int ii = 0; ii < 2; ii++)
        #pragma unroll
        for (int jb = 0; jb < 8; jb++) acc2[ii][jb] = 0ull;

    {
        const ulonglong2* vbs2 = (const ulonglong2*)Vbs;
        const ulonglong2* us2  = (const ulonglong2*)Us;
        const ulonglong2* a2   = (const ulonglong2*)as_;
        for (int dc = 0; dc < 32; dc++) {
            const ulonglong2 u0 = us2[i0*33 + dc];
            const ulonglong2 u1 = us2[i1*33 + dc];
            const ulonglong2 av = a2[dc];
            #pragma unroll
            for (int jb = 0; jb < 8; jb++) {
                const ulonglong2 vv = vbs2[(jb*32 + l)*33 + dc];
                u64 z;
                z = addx2(u0.x, vv.x); acc2[0][jb] = fmax2p(av.x, z & ABSMASK2, acc2[0][jb]);
                z = addx2(u0.y, vv.y); acc2[0][jb] = fmax2p(av.y, z & ABSMASK2, acc2[0][jb]);
                z = addx2(u1.x, vv.x); acc2[1][jb] = fmax2p(av.x, z & ABSMASK2, acc2[1][jb]);
                z = addx2(u1.y, vv.y); acc2[1][jb] = fmax2p(av.y, z & ABSMASK2, acc2[1][jb]);
            }
        }
    }

    // ---- finish e, softmax over j (in-warp), stash weights ----
    #pragma unroll
    for (int ii = 0; ii < 2; ii++) {
        const int il = i0 + ii;
        const int ig = igbase + il;
        const float P = Ps[il];
        const float* brow = bias + ig*K_;
        float e[8];
        float m = -1e30f;
        #pragma unroll
        for (int jb = 0; jb < 8; jb++) {
            const int j = jb*32 + l;
            const float A = lo32(acc2[ii][jb]) + hi32(acc2[ii][jb]);
            const float ev = fmaf(C_LIN, P + Qs[j], fmaf(C_ABS, A, brow[j]));
            e[jb] = ev;
            m = fmaxf(m, ev);
        }
        #pragma unroll
        for (int off = 16; off; off >>= 1)
            m = fmaxf(m, __shfl_xor_sync(0xffffffffu, m, off));
        float s = 0.f;
        #pragma unroll
        for (int jb = 0; jb < 8; jb++) { e[jb] = __expf(e[jb] - m); s += e[jb]; }
        #pragma unroll
        for (int off = 16; off; off >>= 1)
            s += __shfl_xor_sync(0xffffffffu, s, off);
        const float inv = __fdividef(1.f, s);
        #pragma unroll
        for (int jb = 0; jb < 8; jb++)
            ws[(jb*32 + l)*34 + il] = e[jb] * inv;
    }
    __syncthreads();

    // ---- overlay x[b] onto the (now dead) Vb smem region ----
    {
        float4*       xs4 = (float4*)sm;
        const float4* xg4 = (const float4*)x + b * (K_*T_/4);
        for (int idx = tid; idx < K_*T_/4; idx += 512) xs4[idx] = xg4[idx];
    }
    __syncthreads();

    // ---- epilogue (packed): h[i, t-pair] = sigmoid( sum_j w_ij * x[b,j,tp] )
    {
        const u64* xs2 = (const u64*)sm;     // x[j][t] as t-pairs
        u64 h0 = 0ull, h1 = 0ull;            // (h[i0,2l], h[i0,2l+1]) etc.
        #pragma unroll 8
        for (int j = 0; j < K_; j++) {
            const float2 wv = *(const float2*)(ws + j*34 + i0);  // broadcast
            const u64 xv = xs2[j*32 + l];
            h0 = fmax2p(dup2(wv.x), xv, h0);
            h1 = fmax2p(dup2(wv.y), xv, h1);
        }
        const int row0 = (b*K_ + igbase + i0)*T_ + 2*l;
        const int row1 = row0 + T_;
        float2 o0, o1;
        o0.x = __fdividef(1.f, 1.f + __expf(-lo32(h0)));
        o0.y = __fdividef(1.f, 1.f + __expf(-hi32(h0)));
        o1.x = __fdividef(1.f, 1.f + __expf(-lo32(h1)));
        o1.y = __fdividef(1.f, 1.f + __expf(-hi32(h1)));
        *(float2*)(out + row0) = o0;
        *(float2*)(out + row1) = o1;
    }
}

// ---------------------------------------------------------------------------
extern "C" void kernel_launch(void* const* d_in, const int* in_sizes, int n_in,
                              void* d_out, int out_size)
{
    const float* x     = (const float*)d_in[0];
    // d_in[1] = embedding (unused by the reference computation)
    const float* W     = (const float*)d_in[2];
    const float* b_lin = (const float*)d_in[3];
    const float* a     = (const float*)d_in[4];
    const float* bias  = (const float*)d_in[5];
    float* out = (float*)d_out;

    const int smemA = KA_SMEM_FLOATS * 4;   // 78336 B
    const int smemB = KB_SMEM_FLOATS * 4;   // 188544 B
    cudaFuncSetAttribute(kA, cudaFuncAttributeMaxDynamicSharedMemorySize, smemA);
    cudaFuncSetAttribute(kB, cudaFuncAttributeMaxDynamicSharedMemorySize, smemB);

    kA<<<128, 256, smemA>>>(x, W, b_lin);
    kB<<<dim3(8, 16), 512, smemB>>>(x, a, bias, out);
}